// round 6
// baseline (speedup 1.0000x reference)
#include <cuda_runtime.h>
#include <cuda_bf16.h>
#include <cstdint>

// B=16, K=32, H=W=28, HID=OUT=64, NOPS=8, N = B*K = 512 images
#define NIMG 512
#define FC_SPLIT 28
#define FC_SLICE 112     // 3136 / 28

typedef unsigned long long ull;

// ---------------- packed fp32x2 helpers ----------------------------------------
__device__ __forceinline__ ull pk2(float lo, float hi) {
    ull d;
    asm("mov.b64 %0, {%1, %2};" : "=l"(d)
        : "r"(__float_as_uint(lo)), "r"(__float_as_uint(hi)));
    return d;
}
__device__ __forceinline__ float2 upk2(ull v) {
    unsigned int lo, hi;
    asm("mov.b64 {%0, %1}, %2;" : "=r"(lo), "=r"(hi) : "l"(v));
    float2 f; f.x = __uint_as_float(lo); f.y = __uint_as_float(hi);
    return f;
}
__device__ __forceinline__ ull f2fma(ull a, ull b, ull c) {
    ull d;
    asm("fma.rn.f32x2 %0, %1, %2, %3;" : "=l"(d) : "l"(a), "l"(b), "l"(c));
    return d;
}

// ---------------- mma.sync bf16 (sm_80+, assembles under compute_103) ----------
__device__ __forceinline__ void mma_bf16(float* d, const uint32_t* a,
                                         const uint32_t* b) {
    asm volatile(
        "mma.sync.aligned.m16n8k16.row.col.f32.bf16.bf16.f32 "
        "{%0,%1,%2,%3}, {%4,%5,%6,%7}, {%8,%9}, {%0,%1,%2,%3};"
        : "+f"(d[0]), "+f"(d[1]), "+f"(d[2]), "+f"(d[3])
        : "r"(a[0]), "r"(a[1]), "r"(a[2]), "r"(a[3]), "r"(b[0]), "r"(b[1]));
}

// ---------------- scratch -----------------------------------------------------
__device__ float g_h1p[NIMG * 32 * 14 * 14];
__device__ float g_h2p[NIMG * 64 * 7 * 7];
__device__ float g_feat[NIMG * 64];
__device__ float g_wt[8 * 64 * 64];              // eq_w transposed: [o][d*64+e]
__device__ float g_fcpart[FC_SPLIT * NIMG * 64];
__device__ __nv_bfloat16 g_p_hi[16 * 1024 * 64]; // pair products, split
__device__ __nv_bfloat16 g_p_lo[16 * 1024 * 64];
__device__ __nv_bfloat16 g_wkt_hi[16 * 2048 * 64]; // WK^T [b][k*64+e][d], split
__device__ __nv_bfloat16 g_wkt_lo[16 * 2048 * 64];
__device__ float g_row[16 * 32 * 32 * 64];       // [b][k][i][e] (+R folded)
__device__ float g_col[16 * 32 * 32 * 64];       // [b][k][j][e]
__device__ float g_eqpart[2048 * 64];            // per-CTA e-partials

// ---------------- kernel 0: transpose eq_w ------------------------------------
__global__ void k_prep(const float* __restrict__ eq_w) {
    int gid = blockIdx.x * blockDim.x + threadIdx.x;
    int nth = gridDim.x * blockDim.x;
    for (int idx = gid; idx < 8 * 64 * 64; idx += nth) {
        int o = idx & 7;
        int de = idx >> 3;
        g_wt[o * 4096 + de] = eq_w[idx];
    }
}

// ---------------- kernel 1: conv1(1->32) + relu + maxpool2 --------------------
__global__ void __launch_bounds__(224) k_conv1(const float* __restrict__ x,
                                               const float* __restrict__ w,
                                               const float* __restrict__ bias) {
    __shared__ float smin[784];
    __shared__ float smw[288];
    __shared__ float smb[32];
    int n = blockIdx.x;
    int tid = threadIdx.x;
    for (int idx = tid; idx < 784; idx += 224) smin[idx] = x[n * 784 + idx];
    for (int idx = tid; idx < 288; idx += 224) smw[idx] = w[idx];
    if (tid < 32) smb[tid] = bias[tid];
    __syncthreads();

    if (tid < 196) {
        int oy = tid / 14, ox = tid % 14;
        float patch[4][4];
#pragma unroll
        for (int r = 0; r < 4; r++) {
            int y = oy * 2 - 1 + r;
#pragma unroll
            for (int cc = 0; cc < 4; cc++) {
                int xx = ox * 2 - 1 + cc;
                patch[r][cc] = (y >= 0 && y < 28 && xx >= 0 && xx < 28)
                                   ? smin[y * 28 + xx] : 0.f;
            }
        }
        ull pp[4][3];
#pragma unroll
        for (int r = 0; r < 4; r++)
#pragma unroll
            for (int kx = 0; kx < 3; kx++)
                pp[r][kx] = pk2(patch[r][kx], patch[r][kx + 1]);

#pragma unroll 4
        for (int co = 0; co < 32; co++) {
            float b0 = smb[co];
            ull accT = pk2(b0, b0);
            ull accB = pk2(b0, b0);
            const float* wp = smw + co * 9;
#pragma unroll
            for (int ky = 0; ky < 3; ky++)
#pragma unroll
                for (int kx = 0; kx < 3; kx++) {
                    float wv = wp[ky * 3 + kx];
                    ull w2 = pk2(wv, wv);
                    accT = f2fma(pp[ky][kx],     w2, accT);
                    accB = f2fma(pp[ky + 1][kx], w2, accB);
                }
            float2 t = upk2(accT), bt = upk2(accB);
            float m = fmaxf(fmaxf(t.x, t.y), fmaxf(bt.x, bt.y));
            g_h1p[n * 6272 + co * 196 + tid] = fmaxf(m, 0.f);
        }
    }
}

// ---------------- kernel 2: conv2(32->64) + relu + maxpool2 -------------------
__global__ void __launch_bounds__(392) k_conv2(const float* __restrict__ w,
                                               const float* __restrict__ bias) {
    extern __shared__ float sm[];
    float* smin = sm;
    float* smw  = sm + 6272;
    float* smb  = sm + 24704;
    int n = blockIdx.x;
    int tid = threadIdx.x;
    for (int idx = tid; idx < 6272; idx += 392) smin[idx] = g_h1p[n * 6272 + idx];
    for (int idx = tid; idx < 18432; idx += 392) smw[idx] = w[idx];
    if (tid < 64) smb[tid] = bias[tid];
    __syncthreads();

    int cog = tid / 49;
    int pslot = tid - cog * 49;
    int oy = pslot / 7, ox = pslot % 7;

    ull accT[8], accB[8];
#pragma unroll
    for (int c = 0; c < 8; c++) {
        float b0 = smb[cog * 8 + c];
        accT[c] = pk2(b0, b0);
        accB[c] = pk2(b0, b0);
    }

    for (int ci = 0; ci < 32; ci++) {
        const float* ip = smin + ci * 196;
        float patch[4][4];
#pragma unroll
        for (int r = 0; r < 4; r++) {
            int y = oy * 2 - 1 + r;
#pragma unroll
            for (int cc = 0; cc < 4; cc++) {
                int xx = ox * 2 - 1 + cc;
                patch[r][cc] = (y >= 0 && y < 14 && xx >= 0 && xx < 14)
                                   ? ip[y * 14 + xx] : 0.f;
            }
        }
        ull pp[4][3];
#pragma unroll
        for (int r = 0; r < 4; r++)
#pragma unroll
            for (int kx = 0; kx < 3; kx++)
                pp[r][kx] = pk2(patch[r][kx], patch[r][kx + 1]);

#pragma unroll
        for (int c = 0; c < 8; c++) {
            const float* wp = smw + ((cog * 8 + c) * 32 + ci) * 9;
#pragma unroll
            for (int ky = 0; ky < 3; ky++)
#pragma unroll
                for (int kx = 0; kx < 3; kx++) {
                    float wv = wp[ky * 3 + kx];
                    ull w2 = pk2(wv, wv);
                    accT[c] = f2fma(pp[ky][kx],     w2, accT[c]);
                    accB[c] = f2fma(pp[ky + 1][kx], w2, accB[c]);
                }
        }
    }
#pragma unroll
    for (int c = 0; c < 8; c++) {
        float2 t = upk2(accT[c]), bt = upk2(accB[c]);
        float m = fmaxf(fmaxf(t.x, t.y), fmaxf(bt.x, bt.y));
        g_h2p[n * 3136 + (cog * 8 + c) * 49 + pslot] = fmaxf(m, 0.f);
    }
}

// ---------------- kernel 3: fc GEMM -------------------------------------------
__global__ void __launch_bounds__(256) k_fc(const float* __restrict__ fcw) {
    __shared__ float As[16][68];
    __shared__ float Bs[16][68];
    int mt = blockIdx.x / FC_SPLIT, ks = blockIdx.x - mt * FC_SPLIT;
    int n0 = mt * 64, kbase = ks * FC_SLICE;
    int tid = threadIdx.x;
    int ty = tid >> 4, tx = tid & 15;
    int lrow = tid >> 2;
    int lkq  = tid & 3;

    float acc[4][4] = {};
    for (int kb = 0; kb < FC_SLICE; kb += 16) {
        float4 a4 = *(const float4*)&g_h2p[(n0 + lrow) * 3136 + kbase + kb + lkq * 4];
        float4 b4 = *(const float4*)&fcw[lrow * 3136 + kbase + kb + lkq * 4];
        __syncthreads();
        As[lkq * 4 + 0][lrow] = a4.x; As[lkq * 4 + 1][lrow] = a4.y;
        As[lkq * 4 + 2][lrow] = a4.z; As[lkq * 4 + 3][lrow] = a4.w;
        Bs[lkq * 4 + 0][lrow] = b4.x; Bs[lkq * 4 + 1][lrow] = b4.y;
        Bs[lkq * 4 + 2][lrow] = b4.z; Bs[lkq * 4 + 3][lrow] = b4.w;
        __syncthreads();
#pragma unroll
        for (int kk = 0; kk < 16; kk++) {
            float4 av = *(const float4*)&As[kk][ty * 4];
            float4 bv = *(const float4*)&Bs[kk][tx * 4];
            float a[4] = {av.x, av.y, av.z, av.w};
            float bb[4] = {bv.x, bv.y, bv.z, bv.w};
#pragma unroll
            for (int m = 0; m < 4; m++)
#pragma unroll
                for (int nn = 0; nn < 4; nn++)
                    acc[m][nn] = fmaf(a[m], bb[nn], acc[m][nn]);
        }
    }
    float* outp = g_fcpart + ks * (NIMG * 64);
#pragma unroll
    for (int m = 0; m < 4; m++)
#pragma unroll
        for (int nn = 0; nn < 4; nn++)
            outp[(n0 + ty * 4 + m) * 64 + tx * 4 + nn] = acc[m][nn];
}

__global__ void __launch_bounds__(512) k_fcred(const float* __restrict__ fcb) {
    int idx = blockIdx.x * 512 + threadIdx.x;
    float s = 0.f;
#pragma unroll
    for (int r = 0; r < FC_SPLIT; r++) s += g_fcpart[r * (NIMG * 64) + idx];
    g_feat[idx] = fmaxf(s + fcb[idx & 63], 0.f);
}

// ---------------- kernel P: pair products, bf16 split --------------------------
__global__ void __launch_bounds__(256) k_pair() {
    int gid = blockIdx.x * 256 + threadIdx.x;     // grid 512 -> stride 131072
    for (int idx = gid; idx < 16 * 1024 * 64; idx += 512 * 256) {
        int b = idx >> 16;
        int m = (idx >> 6) & 1023;
        int d = idx & 63;
        int i = m >> 5, j = m & 31;
        float p = g_feat[(b * 32 + i) * 64 + d] * g_feat[(b * 32 + j) * 64 + d];
        __nv_bfloat16 hi = __float2bfloat16(p);
        __nv_bfloat16 lo = __float2bfloat16(p - __bfloat162float(hi));
        g_p_hi[idx] = hi;
        g_p_lo[idx] = lo;
    }
}

// ---------------- kernel RCW: rank-1 terms + transposed split WK ---------------
__global__ void __launch_bounds__(256) k_rcw(const float* __restrict__ eq_b) {
    __shared__ float At[64 * 36];
    __shared__ float T[4096];
    __shared__ float S[64];
    __shared__ float Rl[64];
    int b = blockIdx.x >> 5;
    int k = blockIdx.x & 31;
    int tid = threadIdx.x;

    const float* W0 = g_wt;
    const float* W1 = g_wt + 1 * 4096;
    const float* W2 = g_wt + 2 * 4096;
    const float* W3 = g_wt + 3 * 4096;
    const float* W4 = g_wt + 4 * 4096;
    const float* W5 = g_wt + 5 * 4096;
    const float* W6 = g_wt + 6 * 4096;
    const float* W7 = g_wt + 7 * 4096;

    for (int idx = tid; idx < 2048; idx += 256) {
        int i = idx >> 6, d = idx & 63;
        At[d * 36 + i] = g_feat[b * 2048 + idx];
    }
    __syncthreads();
    if (tid < 64) {
        float a = 0.f;
#pragma unroll
        for (int i = 0; i < 32; i++) a += At[tid * 36 + i];
        S[tid] = a * (1.f / 32.f);
    }
    __syncthreads();

    for (int idx = tid; idx < 4096; idx += 256) {
        int d = idx >> 6;
        float sd = S[d];
        T[idx] = sd * fmaf(At[d * 36 + k], W2[idx], sd * W6[idx]);
    }
    if (tid < 64) {
        float acc = 0.f;
        for (int d = 0; d < 64; d++) {
            float sd = S[d];
            acc += sd * sd * fmaf(At[d * 36 + k], W4[d * 64 + tid], sd * W7[d * 64 + tid]);
        }
        Rl[tid] = acc + eq_b[tid];
    }
    __syncthreads();

    // ROW (+R) -> global
    for (int idx = tid; idx < 2048; idx += 256) {
        int i = idx >> 6, e = idx & 63;
        float acc = 0.f;
#pragma unroll 8
        for (int d = 0; d < 64; d++) acc = fmaf(At[d * 36 + i], T[d * 64 + e], acc);
        g_row[(b * 32 + k) * 2048 + idx] = acc + Rl[e];
    }
    __syncthreads();

    for (int idx = tid; idx < 4096; idx += 256) {
        int d = idx >> 6;
        float sd = S[d];
        T[idx] = sd * fmaf(At[d * 36 + k], W1[idx], sd * W5[idx]);
    }
    __syncthreads();

    // COL -> global [j][e]
    for (int idx = tid; idx < 2048; idx += 256) {
        int j = idx >> 6, e = idx & 63;
        float acc = 0.f;
#pragma unroll 8
        for (int d = 0; d < 64; d++) acc = fmaf(At[d * 36 + j], T[d * 64 + e], acc);
        g_col[(b * 32 + k) * 2048 + idx] = acc;
    }

    // WK^T split: [b][k*64 + e][d]
    for (int idx = tid; idx < 4096; idx += 256) {
        int e = idx >> 6, d = idx & 63;
        float wk = fmaf(At[d * 36 + k], W0[d * 64 + e], S[d] * W3[d * 64 + e]);
        __nv_bfloat16 hi = __float2bfloat16(wk);
        __nv_bfloat16 lo = __float2bfloat16(wk - __bfloat162float(hi));
        int o = (b * 2048 + k * 64 + e) * 64 + d;
        g_wkt_hi[o] = hi;
        g_wkt_lo[o] = lo;
    }
}

// ---------------- kernel EQMM: mma.sync bf16 GEMM + fused epilogue -------------
// grid = 16 b x 8 mt x 16 nt. CTA tile M=128 pairs, N=128 (2 k-groups x 64 e),
// K=64. 8 warps: warpM = wid&3 (32 rows), warpN = wid>>2 (64 cols).
// D = Ph@Wh + Ph@Wl + Pl@Wh. Epilogue: +ROW+COL, relu, reduce over m.
#define SM_AH   0
#define SM_AL   18432
#define SM_BH   36864
#define SM_BL   55296
#define SM_ROWO 73728    // 512 floats  [kk][i][e]
#define SM_COLO 75776    // 2*32*65 floats, [kk][j*65+e]
#define SM_PARTO 92416   // 4*128 floats
#define SM_EQ_TOTAL 94464

__global__ void __launch_bounds__(256) k_eqmm() {
    extern __shared__ char smx[];
    int tid = threadIdx.x, wid = tid >> 5, lane = tid & 31;
    int g = lane >> 2, q = lane & 3;
    int cta = blockIdx.x;
    int b = cta >> 7, mt = (cta >> 4) & 7, nt = cta & 15;
    int warpM = wid & 3, warpN = wid >> 2;

    // stage A (128 x 64 bf16, row stride 72 halves = 144B), hi+lo
    {
        const ull* ph = (const ull*)g_p_hi;
        const ull* pl = (const ull*)g_p_lo;
        int rowbase = (b * 1024 + mt * 128) * 8;   // 8 ull per 64-bf16 row
        for (int idx = tid; idx < 1024; idx += 256) {
            int r = idx >> 3, qq = idx & 7;
            *(ull*)(smx + SM_AH + r * 144 + qq * 16 + 0) = ph[rowbase + r * 8 + qq];
            *(ull*)(smx + SM_AL + r * 144 + qq * 16 + 0) = pl[rowbase + r * 8 + qq];
        }
    }
    // oops: 64 bf16 = 128B = 16 ull? 64*2B = 128B = 16 x 8B. Use 16 ull/row.
    // (handled below — the loop above covers 8 ull; do the other 8 here)
    {
        const ull* ph = (const ull*)g_p_hi;
        const ull* pl = (const ull*)g_p_lo;
        int rowbase = (b * 1024 + mt * 128) * 16;
        for (int idx = tid; idx < 2048; idx += 256) {
            int r = idx >> 4, qq = idx & 15;
            *(ull*)(smx + SM_AH + r * 144 + qq * 8) = ph[rowbase + r * 16 + qq];
            *(ull*)(smx + SM_AL + r * 144 + qq * 8) = pl[rowbase + r * 16 + qq];
        }
    }
    // stage B (128 x 64 bf16), hi+lo
    {
        const ull* wh = (const ull*)g_wkt_hi;
        const ull* wl = (const ull*)g_wkt_lo;
        int rowbase = (b * 2048 + nt * 128) * 16;
        for (int idx = tid; idx < 2048; idx += 256) {
            int r = idx >> 4, qq = idx & 15;
            *(ull*)(smx + SM_BH + r * 144 + qq * 8) = wh[rowbase + r * 16 + qq];
            *(ull*)(smx + SM_BL + r * 144 + qq * 8) = wl[rowbase + r * 16 + qq];
        }
    }
    // stage ROW [kk(2)][i(4)][e(64)] and COL [kk(2)][j(32) stride 65][e]
    {
        float* sROW = (float*)(smx + SM_ROWO);
        float* sCOL = (float*)(smx + SM_COLO);
        for (int idx = tid; idx < 512; idx += 256) {
            int kk = idx >> 8, i = (idx >> 6) & 3, e = idx & 63;
            sROW[idx] = g_row[(b * 32 + nt * 2 + kk) * 2048 + (mt * 4 + i) * 64 + e];
        }
        for (int idx = tid; idx < 4096; idx += 256) {
            int kk = idx >> 11, rest = idx & 2047;
            int j = rest >> 6, e = rest & 63;
            sCOL[kk * 2080 + j * 65 + e] =
                g_col[(b * 32 + nt * 2 + kk) * 2048 + rest];
        }
    }
    __syncthreads();

    // ---- MMA mainloop ----
    float acc[2][8][4];
#pragma unroll
    for (int m = 0; m < 2; m++)
#pragma unroll
        for (int n = 0; n < 8; n++)
#pragma unroll
            for (int c = 0; c < 4; c++) acc[m][n][c] = 0.f;

    const char* pAh = smx + SM_AH;
    const char* pAl = smx + SM_AL;
    const char* pBh = smx + SM_BH;
    const char* pBl = smx + SM_BL;

#pragma unroll
    for (int ks = 0; ks < 4; ks++) {
        int kcol = ks * 32 + q * 4;          // byte offset within 144B row
        uint32_t ah[2][4], al[2][4], bh[8][2], bl[8][2];
#pragma unroll
        for (int m = 0; m < 2; m++) {
            int r0 = warpM * 32 + m * 16 + g;
            ah[m][0] = *(const uint32_t*)(pAh + r0 * 144 + kcol);
            ah[m][1] = *(const uint32_t*)(pAh + (r0 + 8) * 144 + kcol);
            ah[m][2] = *(const uint32_t*)(pAh + r0 * 144 + kcol + 16);
            ah[m][3] = *(const uint32_t*)(pAh + (r0 + 8) * 144 + kcol + 16);
            al[m][0] = *(const uint32_t*)(pAl + r0 * 144 + kcol);
            al[m][1] = *(const uint32_t*)(pAl + (r0 + 8) * 144 + kcol);
            al[m][2] = *(const uint32_t*)(pAl + r0 * 144 + kcol + 16);
            al[m][3] = *(const uint32_t*)(pAl + (r0 + 8) * 144 + kcol + 16);
        }
#pragma unroll
        for (int n = 0; n < 8; n++) {
            int n0 = warpN * 64 + n * 8 + g;
            bh[n][0] = *(const uint32_t*)(pBh + n0 * 144 + kcol);
            bh[n][1] = *(const uint32_t*)(pBh + n0 * 144 + kcol + 16);
            bl[n][0] = *(const uint32_t*)(pBl + n0 * 144 + kcol);
            bl[n][1] = *(const uint32_t*)(pBl + n0 * 144 + kcol + 16);
        }
#pragma unroll
        for (int m = 0; m < 2; m++)
#pragma unroll
            for (int n = 0; n < 8; n++) {
                mma_bf16(acc[m][n], ah[m], bh[n]);
                mma_bf16(acc[m][n], ah[m], bl[n]);
                mma_bf16(acc[m][n], al[m], bh[n]);
            }
    }

    // ---- epilogue: +ROW +COL, relu, reduce over rows ----
    const float* sROW = (const float*)(smx + SM_ROWO);
    const float* sCOL = (const float*)(smx + SM_COLO);
    // kk = warpN, i_local = warpM (both warp-uniform)
    const float* rowp = sROW + (warpN * 4 + warpM) * 64;
    const float* colp = sCOL + warpN * 2080;

    float colsum[8][2];
#pragma unroll
    for (int n = 0; n < 8; n++) { colsum[n][0] = 0.f; colsum[n][1] = 0.f; }

#pragma unroll
    for (int m = 0; m < 2; m++)
#pragma unroll
        for (int half = 0; half < 2; half++) {
            int j = m * 16 + g + half * 8;   // row & 31
            const float* cj = colp + j * 65;
#pragma unroll
            for (int n = 0; n < 8; n++) {
                int e0 = n * 8 + 2 * q;
                float v0 = acc[m][n][half * 2 + 0] + rowp[e0]     + cj[e0];
                float v1 = acc[m][n][half * 2 + 1] + rowp[e0 + 1] + cj[e0 + 1];
                colsum[n][0] += fmaxf(v0, 0.f);
                colsum[n][1] += fmaxf(v1, 0.f);
            }
        }

#pragma unroll
    for (int off = 16; off >= 4; off >>= 1)
#pragma unroll
        for (int n = 0; n < 8; n++) {
            colsum[n][0] += __shfl_down_sync(0xffffffffu, colsum[n][0], off);
            colsum[n][1] += __shfl_down_sync(0xffffffffu, colsum[n][1], off);
        }

    float* sPart = (float*)(smx + SM_PARTO);
    __syncthreads();      // COL area no longer needed; sPart region is separate
    if (lane < 4) {
#pragma unroll
        for (int n = 0; n < 8; n++) {
            int c = warpN * 64 + n * 8 + 2 * lane;
            sPart[warpM * 128 + c]     = colsum[n][0];
            sPart[warpM * 128 + c + 1] = colsum[n][1];
        }
    }
    __syncthreads();

    if (tid < 64) {
        float s = 0.f;
#pragma unroll
        for (int wm = 0; wm < 4; wm++)
            s += sPart[wm * 128 + tid] + sPart[wm * 128 + 64 + tid];
        g_eqpart[cta * 64 + tid] = s;
    }
}

// ---------------- kernel 5: reduce, relu, final linear -------------------------
__global__ void __launch_bounds__(512) k_out2(const float* __restrict__ out_w,
                                              const float* __restrict__ out_b,
                                              float* __restrict__ out) {
    int tid = threadIdx.x;
    int bb = tid >> 5;
    int lane = tid & 31;
    const float* base = g_eqpart + bb * (128 * 64);
    float a0 = 0.f, a1 = 0.f;
    for (int t = 0; t < 128; t++) {
        a0 += base[t * 64 + lane];
        a1 += base[t * 64 + lane + 32];
    }
    float x0 = fmaxf(a0 * (1.f / 32768.f), 0.f);
    float x1 = fmaxf(a1 * (1.f / 32768.f), 0.f);
    float acc = x0 * out_w[lane] + x1 * out_w[lane + 32];
#pragma unroll
    for (int off = 16; off; off >>= 1)
        acc += __shfl_down_sync(0xffffffffu, acc, off);
    if (lane == 0) out[bb] = acc + out_b[0];
}

// ---------------- launch ------------------------------------------------------
extern "C" void kernel_launch(void* const* d_in, const int* in_sizes, int n_in,
                              void* d_out, int out_size) {
    const float* x       = (const float*)d_in[0];
    const float* conv1_w = (const float*)d_in[1];
    const float* conv1_b = (const float*)d_in[2];
    const float* conv2_w = (const float*)d_in[3];
    const float* conv2_b = (const float*)d_in[4];
    const float* fc_w    = (const float*)d_in[5];
    const float* fc_b    = (const float*)d_in[6];
    const float* eq_w    = (const float*)d_in[7];
    const float* eq_b    = (const float*)d_in[8];
    const float* out_w   = (const float*)d_in[9];
    const float* out_b   = (const float*)d_in[10];
    float* out = (float*)d_out;

    cudaFuncSetAttribute(k_conv2, cudaFuncAttributeMaxDynamicSharedMemorySize, 99072);
    cudaFuncSetAttribute(k_eqmm,  cudaFuncAttributeMaxDynamicSharedMemorySize, SM_EQ_TOTAL);

    k_prep<<<16, 256>>>(eq_w);
    k_conv1<<<NIMG, 224>>>(x, conv1_w, conv1_b);
    k_conv2<<<NIMG, 392, 99072>>>(conv2_w, conv2_b);
    k_fc<<<8 * FC_SPLIT, 256>>>(fc_w);
    k_fcred<<<64, 512>>>(fc_b);
    k_pair<<<512, 256>>>();
    k_rcw<<<NIMG, 256>>>(eq_b);
    k_eqmm<<<16 * 8 * 16, 256, SM_EQ_TOTAL>>>();
    k_out2<<<1, 512>>>(out_w, out_b, out);
}

// round 7
// speedup vs baseline: 1.0877x; 1.0877x over previous
#include <cuda_runtime.h>
#include <cuda_bf16.h>
#include <cstdint>

// B=16, K=32, H=W=28, HID=OUT=64, NOPS=8, N = B*K = 512 images
#define NIMG 512
#define FC_SPLIT 28
#define FC_SLICE 112     // 3136 / 28

typedef unsigned long long ull;

// ---------------- packed fp32x2 helpers ----------------------------------------
__device__ __forceinline__ ull pk2(float lo, float hi) {
    ull d;
    asm("mov.b64 %0, {%1, %2};" : "=l"(d)
        : "r"(__float_as_uint(lo)), "r"(__float_as_uint(hi)));
    return d;
}
__device__ __forceinline__ float2 upk2(ull v) {
    unsigned int lo, hi;
    asm("mov.b64 {%0, %1}, %2;" : "=r"(lo), "=r"(hi) : "l"(v));
    float2 f; f.x = __uint_as_float(lo); f.y = __uint_as_float(hi);
    return f;
}
__device__ __forceinline__ ull f2fma(ull a, ull b, ull c) {
    ull d;
    asm("fma.rn.f32x2 %0, %1, %2, %3;" : "=l"(d) : "l"(a), "l"(b), "l"(c));
    return d;
}

// ---------------- scratch -----------------------------------------------------
__device__ float g_h1p[NIMG * 32 * 14 * 14];     // conv1+relu+pool out
__device__ float g_h2p[NIMG * 64 * 7 * 7];       // conv2+relu+pool out
__device__ float g_feat[NIMG * 64];              // fc+relu out
__device__ float g_wt[8 * 64 * 64];              // eq_w transposed: [o][d*64+e]
__device__ float g_part[NIMG * 64];              // per-(b,k) partial relu-sums
__device__ float g_fcpart[FC_SPLIT * NIMG * 64]; // fc k-split partials

// ---------------- kernel 0: transpose eq_w ------------------------------------
__global__ void k_prep(const float* __restrict__ eq_w) {
    int gid = blockIdx.x * blockDim.x + threadIdx.x;
    int nth = gridDim.x * blockDim.x;
    for (int idx = gid; idx < 8 * 64 * 64; idx += nth) {
        int o = idx & 7;
        int de = idx >> 3;                       // d*64 + e
        g_wt[o * 4096 + de] = eq_w[idx];
    }
}

// ---------------- kernel 1: conv1(1->32) + relu + maxpool2 --------------------
__global__ void __launch_bounds__(224) k_conv1(const float* __restrict__ x,
                                               const float* __restrict__ w,
                                               const float* __restrict__ bias) {
    __shared__ float smin[784];
    __shared__ float smw[288];
    __shared__ float smb[32];
    int n = blockIdx.x;
    int tid = threadIdx.x;
    for (int idx = tid; idx < 784; idx += 224) smin[idx] = x[n * 784 + idx];
    for (int idx = tid; idx < 288; idx += 224) smw[idx] = w[idx];
    if (tid < 32) smb[tid] = bias[tid];
    __syncthreads();

    if (tid < 196) {
        int oy = tid / 14, ox = tid % 14;
        float patch[4][4];
#pragma unroll
        for (int r = 0; r < 4; r++) {
            int y = oy * 2 - 1 + r;
#pragma unroll
            for (int cc = 0; cc < 4; cc++) {
                int xx = ox * 2 - 1 + cc;
                patch[r][cc] = (y >= 0 && y < 28 && xx >= 0 && xx < 28)
                                   ? smin[y * 28 + xx] : 0.f;
            }
        }
        ull pp[4][3];
#pragma unroll
        for (int r = 0; r < 4; r++)
#pragma unroll
            for (int kx = 0; kx < 3; kx++)
                pp[r][kx] = pk2(patch[r][kx], patch[r][kx + 1]);

#pragma unroll 4
        for (int co = 0; co < 32; co++) {
            float b0 = smb[co];
            ull accT = pk2(b0, b0);
            ull accB = pk2(b0, b0);
            const float* wp = smw + co * 9;
#pragma unroll
            for (int ky = 0; ky < 3; ky++)
#pragma unroll
                for (int kx = 0; kx < 3; kx++) {
                    float wv = wp[ky * 3 + kx];
                    ull w2 = pk2(wv, wv);
                    accT = f2fma(pp[ky][kx],     w2, accT);
                    accB = f2fma(pp[ky + 1][kx], w2, accB);
                }
            float2 t = upk2(accT), bt = upk2(accB);
            float m = fmaxf(fmaxf(t.x, t.y), fmaxf(bt.x, bt.y));
            g_h1p[n * 6272 + co * 196 + tid] = fmaxf(m, 0.f);
        }
    }
}

// ---------------- kernel 2: conv2(32->64) + relu + maxpool2 -------------------
__global__ void __launch_bounds__(392) k_conv2(const float* __restrict__ w,
                                               const float* __restrict__ bias) {
    extern __shared__ float sm[];
    float* smin = sm;
    float* smw  = sm + 6272;
    float* smb  = sm + 24704;
    int n = blockIdx.x;
    int tid = threadIdx.x;
    for (int idx = tid; idx < 6272; idx += 392) smin[idx] = g_h1p[n * 6272 + idx];
    for (int idx = tid; idx < 18432; idx += 392) smw[idx] = w[idx];
    if (tid < 64) smb[tid] = bias[tid];
    __syncthreads();

    int cog = tid / 49;
    int pslot = tid - cog * 49;
    int oy = pslot / 7, ox = pslot % 7;

    ull accT[8], accB[8];
#pragma unroll
    for (int c = 0; c < 8; c++) {
        float b0 = smb[cog * 8 + c];
        accT[c] = pk2(b0, b0);
        accB[c] = pk2(b0, b0);
    }

    for (int ci = 0; ci < 32; ci++) {
        const float* ip = smin + ci * 196;
        float patch[4][4];
#pragma unroll
        for (int r = 0; r < 4; r++) {
            int y = oy * 2 - 1 + r;
#pragma unroll
            for (int cc = 0; cc < 4; cc++) {
                int xx = ox * 2 - 1 + cc;
                patch[r][cc] = (y >= 0 && y < 14 && xx >= 0 && xx < 14)
                                   ? ip[y * 14 + xx] : 0.f;
            }
        }
        ull pp[4][3];
#pragma unroll
        for (int r = 0; r < 4; r++)
#pragma unroll
            for (int kx = 0; kx < 3; kx++)
                pp[r][kx] = pk2(patch[r][kx], patch[r][kx + 1]);

#pragma unroll
        for (int c = 0; c < 8; c++) {
            const float* wp = smw + ((cog * 8 + c) * 32 + ci) * 9;
#pragma unroll
            for (int ky = 0; ky < 3; ky++)
#pragma unroll
                for (int kx = 0; kx < 3; kx++) {
                    float wv = wp[ky * 3 + kx];
                    ull w2 = pk2(wv, wv);
                    accT[c] = f2fma(pp[ky][kx],     w2, accT[c]);
                    accB[c] = f2fma(pp[ky + 1][kx], w2, accB[c]);
                }
        }
    }
#pragma unroll
    for (int c = 0; c < 8; c++) {
        float2 t = upk2(accT[c]), bt = upk2(accB[c]);
        float m = fmaxf(fmaxf(t.x, t.y), fmaxf(bt.x, bt.y));
        g_h2p[n * 3136 + (cog * 8 + c) * 49 + pslot] = fmaxf(m, 0.f);
    }
}

// ---------------- kernel 3: fc GEMM -------------------------------------------
__global__ void __launch_bounds__(256) k_fc(const float* __restrict__ fcw) {
    __shared__ float As[16][68];
    __shared__ float Bs[16][68];
    int mt = blockIdx.x / FC_SPLIT, ks = blockIdx.x - mt * FC_SPLIT;
    int n0 = mt * 64, kbase = ks * FC_SLICE;
    int tid = threadIdx.x;
    int ty = tid >> 4, tx = tid & 15;
    int lrow = tid >> 2;
    int lkq  = tid & 3;

    float acc[4][4] = {};
    for (int kb = 0; kb < FC_SLICE; kb += 16) {
        float4 a4 = *(const float4*)&g_h2p[(n0 + lrow) * 3136 + kbase + kb + lkq * 4];
        float4 b4 = *(const float4*)&fcw[lrow * 3136 + kbase + kb + lkq * 4];
        __syncthreads();
        As[lkq * 4 + 0][lrow] = a4.x; As[lkq * 4 + 1][lrow] = a4.y;
        As[lkq * 4 + 2][lrow] = a4.z; As[lkq * 4 + 3][lrow] = a4.w;
        Bs[lkq * 4 + 0][lrow] = b4.x; Bs[lkq * 4 + 1][lrow] = b4.y;
        Bs[lkq * 4 + 2][lrow] = b4.z; Bs[lkq * 4 + 3][lrow] = b4.w;
        __syncthreads();
#pragma unroll
        for (int kk = 0; kk < 16; kk++) {
            float4 av = *(const float4*)&As[kk][ty * 4];
            float4 bv = *(const float4*)&Bs[kk][tx * 4];
            float a[4] = {av.x, av.y, av.z, av.w};
            float bb[4] = {bv.x, bv.y, bv.z, bv.w};
#pragma unroll
            for (int m = 0; m < 4; m++)
#pragma unroll
                for (int nn = 0; nn < 4; nn++)
                    acc[m][nn] = fmaf(a[m], bb[nn], acc[m][nn]);
        }
    }
    float* outp = g_fcpart + ks * (NIMG * 64);
#pragma unroll
    for (int m = 0; m < 4; m++)
#pragma unroll
        for (int nn = 0; nn < 4; nn++)
            outp[(n0 + ty * 4 + m) * 64 + tx * 4 + nn] = acc[m][nn];
}

__global__ void __launch_bounds__(512) k_fcred(const float* __restrict__ fcb) {
    int idx = blockIdx.x * 512 + threadIdx.x;
    float s = 0.f;
#pragma unroll
    for (int r = 0; r < FC_SPLIT; r++) s += g_fcpart[r * (NIMG * 64) + idx];
    g_feat[idx] = fmaxf(s + fcb[idx & 63], 0.f);
}

// ---------------- kernel 4: equivariant block, symmetric-pair version ----------
// One block per (b,k). Bilinear term M[i,j,e] = sum_d a_i a_j WK[d,e] is
// symmetric in (i,j): compute once per unordered pair (528), apply both
// rank-1 epilogues:  esum += relu(M+ROW[i]+COL[j]+R) + [i!=j] relu(M+ROW[j]+COL[i]+R)
// Warp owns 8 e-channels; each lane handles 2 pairs per chunk (9 chunks x 64).
__global__ void __launch_bounds__(256, 3) k_eq(const float* __restrict__ eq_b) {
    extern __shared__ float sm[];
    float* At   = sm;             // 2304 : At[d*36 + i]
    float* WK   = sm + 2304;      // 4096 : [d*64+e]  (temp T during prologue)
    float* ROWt = sm + 6400;      // 2112 : [e*33 + i]
    float* COLt = sm + 8512;      // 2112 : [e*33 + j]
    float* S    = sm + 10624;     // 64
    float* R    = sm + 10688;     // 64
    int*   ptab = (int*)(sm + 10752); // 576 packed pairs
    // total 11328 floats = 45312 B

    int b = blockIdx.x >> 5;
    int k = blockIdx.x & 31;
    int tid = threadIdx.x, warp = tid >> 5, lane = tid & 31;

    const float* W0 = g_wt;
    const float* W1 = g_wt + 1 * 4096;
    const float* W2 = g_wt + 2 * 4096;
    const float* W3 = g_wt + 3 * 4096;
    const float* W4 = g_wt + 4 * 4096;
    const float* W5 = g_wt + 5 * 4096;
    const float* W6 = g_wt + 6 * 4096;
    const float* W7 = g_wt + 7 * 4096;

    // --- pair table: upper triangle incl. diagonal, 528 real + 48 dummy ------
    for (int p = tid; p < 576; p += 256) {
        int v = 0;
        if (p < 528) {
            int i = (int)floorf((65.0f - sqrtf(4225.0f - 8.0f * (float)p)) * 0.5f);
            if (i < 0) i = 0;
            if (i > 31) i = 31;
            while (i < 31 && 32 * (i + 1) - ((i + 1) * i) / 2 <= p) i++;
            while (i > 0 && 32 * i - (i * (i - 1)) / 2 > p) i--;
            int o = 32 * i - (i * (i - 1)) / 2;
            int j = i + (p - o);
            v = i | (j << 8) | ((j != i ? 1 : 0) << 16) | (1 << 17);
        }
        ptab[p] = v;
    }

    for (int idx = tid; idx < 2048; idx += 256) {
        int i = idx >> 6, d = idx & 63;
        At[d * 36 + i] = g_feat[b * 2048 + idx];
    }
    __syncthreads();
    if (tid < 64) {
        float a = 0.f;
#pragma unroll
        for (int i = 0; i < 32; i++) a += At[tid * 36 + i];
        S[tid] = a * (1.f / 32.f);
    }
    __syncthreads();

    float* T = WK;   // reuse as temp
    for (int idx = tid; idx < 4096; idx += 256) {
        int d = idx >> 6;
        float sd = S[d];
        T[idx] = sd * fmaf(At[d * 36 + k], W2[idx], sd * W6[idx]);
    }
    if (tid < 64) {
        float acc = 0.f;
        for (int d = 0; d < 64; d++) {
            float sd = S[d];
            acc += sd * sd * fmaf(At[d * 36 + k], W4[d * 64 + tid], sd * W7[d * 64 + tid]);
        }
        R[tid] = acc + eq_b[tid];
    }
    __syncthreads();

    // ROWt[e*33+i] = (A @ T_row)[i,e]
    for (int idx = tid; idx < 2048; idx += 256) {
        int i = idx >> 6, e = idx & 63;
        float acc = 0.f;
#pragma unroll 8
        for (int d = 0; d < 64; d++) acc = fmaf(At[d * 36 + i], T[d * 64 + e], acc);
        ROWt[e * 33 + i] = acc;
    }
    __syncthreads();

    for (int idx = tid; idx < 4096; idx += 256) {
        int d = idx >> 6;
        float sd = S[d];
        T[idx] = sd * fmaf(At[d * 36 + k], W1[idx], sd * W5[idx]);
    }
    __syncthreads();

    // COLt[e*33+j] = (A @ T_col)[j,e]
    for (int idx = tid; idx < 2048; idx += 256) {
        int j = idx >> 6, e = idx & 63;
        float acc = 0.f;
#pragma unroll 8
        for (int d = 0; d < 64; d++) acc = fmaf(At[d * 36 + j], T[d * 64 + e], acc);
        COLt[e * 33 + j] = acc;
    }
    __syncthreads();

    // final WK[d,e] = a_k[d]*W0 + s[d]*W3
    for (int idx = tid; idx < 4096; idx += 256) {
        int d = idx >> 6;
        WK[idx] = fmaf(At[d * 36 + k], W0[idx], S[d] * W3[idx]);
    }
    __syncthreads();

    // --- main loop over unordered pairs ---------------------------------------
    int e0 = warp * 8;
    const float* WKe = WK + e0;
    float esum[8] = {0, 0, 0, 0, 0, 0, 0, 0};
    float creg[8];
#pragma unroll
    for (int t = 0; t < 8; t++) creg[t] = R[e0 + t];

    for (int c = 0; c < 9; c++) {
        int vA = ptab[c * 64 + lane];
        int vB = ptab[c * 64 + 32 + lane];
        int iA = vA & 255, jA = (vA >> 8) & 255;
        int iB = vB & 255, jB = (vB >> 8) & 255;
        float wA2 = (float)((vA >> 16) & 1), wA1 = (float)((vA >> 17) & 1);
        float wB2 = (float)((vB >> 16) & 1), wB1 = (float)((vB >> 17) & 1);

        float accA[8] = {0, 0, 0, 0, 0, 0, 0, 0};
        float accB[8] = {0, 0, 0, 0, 0, 0, 0, 0};

#pragma unroll 16
        for (int d = 0; d < 64; d++) {
            float cA = At[d * 36 + iA] * At[d * 36 + jA];
            float cB = At[d * 36 + iB] * At[d * 36 + jB];
            float4 w0 = *(const float4*)(WKe + d * 64);
            float4 w1 = *(const float4*)(WKe + d * 64 + 4);
            accA[0] = fmaf(cA, w0.x, accA[0]); accB[0] = fmaf(cB, w0.x, accB[0]);
            accA[1] = fmaf(cA, w0.y, accA[1]); accB[1] = fmaf(cB, w0.y, accB[1]);
            accA[2] = fmaf(cA, w0.z, accA[2]); accB[2] = fmaf(cB, w0.z, accB[2]);
            accA[3] = fmaf(cA, w0.w, accA[3]); accB[3] = fmaf(cB, w0.w, accB[3]);
            accA[4] = fmaf(cA, w1.x, accA[4]); accB[4] = fmaf(cB, w1.x, accB[4]);
            accA[5] = fmaf(cA, w1.y, accA[5]); accB[5] = fmaf(cB, w1.y, accB[5]);
            accA[6] = fmaf(cA, w1.z, accA[6]); accB[6] = fmaf(cB, w1.z, accB[6]);
            accA[7] = fmaf(cA, w1.w, accA[7]); accB[7] = fmaf(cB, w1.w, accB[7]);
        }

#pragma unroll
        for (int t = 0; t < 8; t++) {
            int e = (e0 + t) * 33;
            float baseA = accA[t] + creg[t];
            float baseB = accB[t] + creg[t];
            float tA1 = baseA + ROWt[e + iA] + COLt[e + jA];
            float tA2 = baseA + ROWt[e + jA] + COLt[e + iA];
            float tB1 = baseB + ROWt[e + iB] + COLt[e + jB];
            float tB2 = baseB + ROWt[e + jB] + COLt[e + iB];
            esum[t] += wA1 * fmaxf(tA1, 0.f) + wA2 * fmaxf(tA2, 0.f)
                     + wB1 * fmaxf(tB1, 0.f) + wB2 * fmaxf(tB2, 0.f);
        }
    }

#pragma unroll
    for (int t = 0; t < 8; t++) {
        float v = esum[t];
#pragma unroll
        for (int off = 16; off; off >>= 1)
            v += __shfl_down_sync(0xffffffffu, v, off);
        if (lane == 0) g_part[blockIdx.x * 64 + e0 + t] = v;
    }
}

// ---------------- kernel 5: reduce over k, relu, final linear -----------------
__global__ void __launch_bounds__(512) k_out(const float* __restrict__ out_w,
                                             const float* __restrict__ out_b,
                                             float* __restrict__ out) {
    int tid = threadIdx.x;
    int bb = tid >> 5;
    int lane = tid & 31;
    float a0 = 0.f, a1 = 0.f;
    for (int k = 0; k < 32; k++) {
        const float* p = g_part + (bb * 32 + k) * 64;
        a0 += p[lane];
        a1 += p[lane + 32];
    }
    float x0 = fmaxf(a0 * (1.f / 32768.f), 0.f);
    float x1 = fmaxf(a1 * (1.f / 32768.f), 0.f);
    float acc = x0 * out_w[lane] + x1 * out_w[lane + 32];
#pragma unroll
    for (int off = 16; off; off >>= 1)
        acc += __shfl_down_sync(0xffffffffu, acc, off);
    if (lane == 0) out[bb] = acc + out_b[0];
}

// ---------------- launch ------------------------------------------------------
extern "C" void kernel_launch(void* const* d_in, const int* in_sizes, int n_in,
                              void* d_out, int out_size) {
    const float* x       = (const float*)d_in[0];
    const float* conv1_w = (const float*)d_in[1];
    const float* conv1_b = (const float*)d_in[2];
    const float* conv2_w = (const float*)d_in[3];
    const float* conv2_b = (const float*)d_in[4];
    const float* fc_w    = (const float*)d_in[5];
    const float* fc_b    = (const float*)d_in[6];
    const float* eq_w    = (const float*)d_in[7];
    const float* eq_b    = (const float*)d_in[8];
    const float* out_w   = (const float*)d_in[9];
    const float* out_b   = (const float*)d_in[10];
    float* out = (float*)d_out;

    cudaFuncSetAttribute(k_conv2, cudaFuncAttributeMaxDynamicSharedMemorySize, 99072);
    cudaFuncSetAttribute(k_eq,    cudaFuncAttributeMaxDynamicSharedMemorySize, 45312);

    k_prep<<<16, 256>>>(eq_w);
    k_conv1<<<NIMG, 224>>>(x, conv1_w, conv1_b);
    k_conv2<<<NIMG, 392, 99072>>>(conv2_w, conv2_b);
    k_fc<<<8 * FC_SPLIT, 256>>>(fc_w);
    k_fcred<<<64, 512>>>(fc_b);
    k_eq<<<NIMG, 256, 45312>>>(eq_b);
    k_out<<<1, 512>>>(out_w, out_b, out);
}

// round 8
// speedup vs baseline: 1.2968x; 1.1922x over previous
#include <cuda_runtime.h>
#include <cuda_bf16.h>
#include <cstdint>

// B=16, K=32, H=W=28, HID=OUT=64, NOPS=8, N = B*K = 512 images
#define NIMG 512
#define FC_SPLIT 49
#define FC_SLICE 64      // 3136 / 49

typedef unsigned long long ull;

// ---------------- packed fp32x2 helpers ----------------------------------------
__device__ __forceinline__ ull pk2(float lo, float hi) {
    ull d;
    asm("mov.b64 %0, {%1, %2};" : "=l"(d)
        : "r"(__float_as_uint(lo)), "r"(__float_as_uint(hi)));
    return d;
}
__device__ __forceinline__ float2 upk2(ull v) {
    unsigned int lo, hi;
    asm("mov.b64 {%0, %1}, %2;" : "=r"(lo), "=r"(hi) : "l"(v));
    float2 f; f.x = __uint_as_float(lo); f.y = __uint_as_float(hi);
    return f;
}
__device__ __forceinline__ ull f2fma(ull a, ull b, ull c) {
    ull d;
    asm("fma.rn.f32x2 %0, %1, %2, %3;" : "=l"(d) : "l"(a), "l"(b), "l"(c));
    return d;
}
__device__ __forceinline__ ull f2mul(ull a, ull b) {
    ull d;
    asm("mul.rn.f32x2 %0, %1, %2;" : "=l"(d) : "l"(a), "l"(b));
    return d;
}

// ---------------- scratch -----------------------------------------------------
__device__ float g_h1p[NIMG * 32 * 14 * 14];     // conv1+relu+pool out
__device__ float g_h2p[NIMG * 64 * 7 * 7];       // conv2+relu+pool out
__device__ float g_feat[NIMG * 64];              // fc+relu out
__device__ float g_wt[8 * 64 * 64];              // eq_w transposed: [o][d*64+e]
__device__ float g_part[NIMG * 64];              // per-(b,k) partial relu-sums
__device__ float g_fcpart[FC_SPLIT * NIMG * 64]; // fc k-split partials
__device__ ull   g_w2[8 * 32 * 9 * 4];           // conv2 weights, channel-pair packed

// ---------------- kernel 0: transpose eq_w + interleave conv2 weights ----------
__global__ void k_prep(const float* __restrict__ eq_w,
                       const float* __restrict__ conv2_w) {
    int gid = blockIdx.x * blockDim.x + threadIdx.x;
    int nth = gridDim.x * blockDim.x;
    for (int idx = gid; idx < 8 * 64 * 64; idx += nth) {
        int o = idx & 7;
        int de = idx >> 3;                       // d*64 + e
        g_wt[o * 4096 + de] = eq_w[idx];
    }
    // g_w2[((cog*32+ci)*9 + k)*4 + t] = {w[cog*8+2t][ci][k], w[cog*8+2t+1][ci][k]}
    for (int idx = gid; idx < 9216; idx += nth) {
        int t = idx & 3;
        int k = (idx >> 2) % 9;
        int rest = idx / 36;                     // cog*32 + ci
        int ci = rest & 31, cog = rest >> 5;
        int co0 = cog * 8 + 2 * t;
        g_w2[idx] = pk2(conv2_w[co0 * 288 + ci * 9 + k],
                        conv2_w[(co0 + 1) * 288 + ci * 9 + k]);
    }
}

// ---------------- kernel 1: conv1(1->32) + relu + maxpool2 --------------------
__global__ void __launch_bounds__(224) k_conv1(const float* __restrict__ x,
                                               const float* __restrict__ w,
                                               const float* __restrict__ bias) {
    __shared__ float smin[784];
    __shared__ float smw[288];
    __shared__ float smb[32];
    int n = blockIdx.x;
    int tid = threadIdx.x;
    for (int idx = tid; idx < 784; idx += 224) smin[idx] = x[n * 784 + idx];
    for (int idx = tid; idx < 288; idx += 224) smw[idx] = w[idx];
    if (tid < 32) smb[tid] = bias[tid];
    __syncthreads();

    if (tid < 196) {
        int oy = tid / 14, ox = tid % 14;
        float patch[4][4];
#pragma unroll
        for (int r = 0; r < 4; r++) {
            int y = oy * 2 - 1 + r;
#pragma unroll
            for (int cc = 0; cc < 4; cc++) {
                int xx = ox * 2 - 1 + cc;
                patch[r][cc] = (y >= 0 && y < 28 && xx >= 0 && xx < 28)
                                   ? smin[y * 28 + xx] : 0.f;
            }
        }
        ull pp[4][3];
#pragma unroll
        for (int r = 0; r < 4; r++)
#pragma unroll
            for (int kx = 0; kx < 3; kx++)
                pp[r][kx] = pk2(patch[r][kx], patch[r][kx + 1]);

#pragma unroll 4
        for (int co = 0; co < 32; co++) {
            float b0 = smb[co];
            ull accT = pk2(b0, b0);
            ull accB = pk2(b0, b0);
            const float* wp = smw + co * 9;
#pragma unroll
            for (int ky = 0; ky < 3; ky++)
#pragma unroll
                for (int kx = 0; kx < 3; kx++) {
                    float wv = wp[ky * 3 + kx];
                    ull w2 = pk2(wv, wv);
                    accT = f2fma(pp[ky][kx],     w2, accT);
                    accB = f2fma(pp[ky + 1][kx], w2, accB);
                }
            float2 t = upk2(accT), bt = upk2(accB);
            float m = fmaxf(fmaxf(t.x, t.y), fmaxf(bt.x, bt.y));
            g_h1p[n * 6272 + co * 196 + tid] = fmaxf(m, 0.f);
        }
    }
}

// ---------------- kernel 2: conv2(32->64) + relu + maxpool2 -------------------
// Channel-pair packed weights (no weight pack MOVs). 392 thr = 8 cog x 49 px.
// smem: smw2 9216 ull (73728B) | smin 6272 f (25088B) | smb 64 f = 99072B.
__global__ void __launch_bounds__(392, 2) k_conv2(const float* __restrict__ bias) {
    extern __shared__ char smraw[];
    ull*   smw2 = (ull*)smraw;
    float* smin = (float*)(smraw + 73728);
    float* smb  = (float*)(smraw + 73728 + 25088);
    int n = blockIdx.x;
    int tid = threadIdx.x;
    for (int idx = tid; idx < 9216; idx += 392) smw2[idx] = g_w2[idx];
    for (int idx = tid; idx < 6272; idx += 392) smin[idx] = g_h1p[n * 6272 + idx];
    if (tid < 64) smb[tid] = bias[tid];
    __syncthreads();

    int cog = tid / 49;
    int pslot = tid - cog * 49;
    int oy = pslot / 7, ox = pslot % 7;

    ull acc[4][4];
#pragma unroll
    for (int t = 0; t < 4; t++) {
        ull bp = pk2(smb[cog * 8 + 2 * t], smb[cog * 8 + 2 * t + 1]);
        acc[t][0] = bp; acc[t][1] = bp; acc[t][2] = bp; acc[t][3] = bp;
    }

    const ull* wbase = smw2 + cog * 32 * 36;
    for (int ci = 0; ci < 32; ci++) {
        const float* ip = smin + ci * 196;
        float patch[4][4];
#pragma unroll
        for (int r = 0; r < 4; r++) {
            int y = oy * 2 - 1 + r;
#pragma unroll
            for (int cc = 0; cc < 4; cc++) {
                int xx = ox * 2 - 1 + cc;
                patch[r][cc] = (y >= 0 && y < 14 && xx >= 0 && xx < 14)
                                   ? ip[y * 14 + xx] : 0.f;
            }
        }
        ull pd[4][4];
#pragma unroll
        for (int r = 0; r < 4; r++)
#pragma unroll
            for (int cc = 0; cc < 4; cc++)
                pd[r][cc] = pk2(patch[r][cc], patch[r][cc]);

        const ull* wci = wbase + ci * 36;
#pragma unroll
        for (int ky = 0; ky < 3; ky++)
#pragma unroll
            for (int kx = 0; kx < 3; kx++) {
                int k = ky * 3 + kx;
                ull w0 = wci[k * 4 + 0];
                ull w1 = wci[k * 4 + 1];
                ull w2 = wci[k * 4 + 2];
                ull w3 = wci[k * 4 + 3];
                acc[0][0] = f2fma(pd[ky][kx],         w0, acc[0][0]);
                acc[0][1] = f2fma(pd[ky][kx + 1],     w0, acc[0][1]);
                acc[0][2] = f2fma(pd[ky + 1][kx],     w0, acc[0][2]);
                acc[0][3] = f2fma(pd[ky + 1][kx + 1], w0, acc[0][3]);
                acc[1][0] = f2fma(pd[ky][kx],         w1, acc[1][0]);
                acc[1][1] = f2fma(pd[ky][kx + 1],     w1, acc[1][1]);
                acc[1][2] = f2fma(pd[ky + 1][kx],     w1, acc[1][2]);
                acc[1][3] = f2fma(pd[ky + 1][kx + 1], w1, acc[1][3]);
                acc[2][0] = f2fma(pd[ky][kx],         w2, acc[2][0]);
                acc[2][1] = f2fma(pd[ky][kx + 1],     w2, acc[2][1]);
                acc[2][2] = f2fma(pd[ky + 1][kx],     w2, acc[2][2]);
                acc[2][3] = f2fma(pd[ky + 1][kx + 1], w2, acc[2][3]);
                acc[3][0] = f2fma(pd[ky][kx],         w3, acc[3][0]);
                acc[3][1] = f2fma(pd[ky][kx + 1],     w3, acc[3][1]);
                acc[3][2] = f2fma(pd[ky + 1][kx],     w3, acc[3][2]);
                acc[3][3] = f2fma(pd[ky + 1][kx + 1], w3, acc[3][3]);
            }
    }
#pragma unroll
    for (int t = 0; t < 4; t++) {
        float2 p0 = upk2(acc[t][0]);
        float2 p1 = upk2(acc[t][1]);
        float2 p2 = upk2(acc[t][2]);
        float2 p3 = upk2(acc[t][3]);
        float m0 = fmaxf(fmaxf(p0.x, p1.x), fmaxf(p2.x, p3.x));
        float m1 = fmaxf(fmaxf(p0.y, p1.y), fmaxf(p2.y, p3.y));
        int co = cog * 8 + 2 * t;
        g_h2p[n * 3136 + co * 49 + pslot]        = fmaxf(m0, 0.f);
        g_h2p[n * 3136 + (co + 1) * 49 + pslot]  = fmaxf(m1, 0.f);
    }
}

// ---------------- kernel 3: fc GEMM -------------------------------------------
// grid = 8 M-tiles x 49 K-splits = 392 blocks; slice 64 = 4 k-chunks of 16.
__global__ void __launch_bounds__(256) k_fc(const float* __restrict__ fcw) {
    __shared__ float As[16][68];
    __shared__ float Bs[16][68];
    int mt = blockIdx.x / FC_SPLIT, ks = blockIdx.x - mt * FC_SPLIT;
    int n0 = mt * 64, kbase = ks * FC_SLICE;
    int tid = threadIdx.x;
    int ty = tid >> 4, tx = tid & 15;
    int lrow = tid >> 2;
    int lkq  = tid & 3;

    float acc[4][4] = {};
    for (int kb = 0; kb < FC_SLICE; kb += 16) {
        float4 a4 = *(const float4*)&g_h2p[(n0 + lrow) * 3136 + kbase + kb + lkq * 4];
        float4 b4 = *(const float4*)&fcw[lrow * 3136 + kbase + kb + lkq * 4];
        __syncthreads();
        As[lkq * 4 + 0][lrow] = a4.x; As[lkq * 4 + 1][lrow] = a4.y;
        As[lkq * 4 + 2][lrow] = a4.z; As[lkq * 4 + 3][lrow] = a4.w;
        Bs[lkq * 4 + 0][lrow] = b4.x; Bs[lkq * 4 + 1][lrow] = b4.y;
        Bs[lkq * 4 + 2][lrow] = b4.z; Bs[lkq * 4 + 3][lrow] = b4.w;
        __syncthreads();
#pragma unroll
        for (int kk = 0; kk < 16; kk++) {
            float4 av = *(const float4*)&As[kk][ty * 4];
            float4 bv = *(const float4*)&Bs[kk][tx * 4];
            float a[4] = {av.x, av.y, av.z, av.w};
            float bb[4] = {bv.x, bv.y, bv.z, bv.w};
#pragma unroll
            for (int m = 0; m < 4; m++)
#pragma unroll
                for (int nn = 0; nn < 4; nn++)
                    acc[m][nn] = fmaf(a[m], bb[nn], acc[m][nn]);
        }
    }
    float* outp = g_fcpart + ks * (NIMG * 64);
#pragma unroll
    for (int m = 0; m < 4; m++)
#pragma unroll
        for (int nn = 0; nn < 4; nn++)
            outp[(n0 + ty * 4 + m) * 64 + tx * 4 + nn] = acc[m][nn];
}

__global__ void __launch_bounds__(512) k_fcred(const float* __restrict__ fcb) {
    int idx = blockIdx.x * 512 + threadIdx.x;
    float s = 0.f;
#pragma unroll
    for (int r = 0; r < FC_SPLIT; r++) s += g_fcpart[r * (NIMG * 64) + idx];
    g_feat[idx] = fmaxf(s + fcb[idx & 63], 0.f);
}

// ---------------- kernel 4: equivariant block (r4 structure, 8-row i-blocks) ---
__global__ void __launch_bounds__(256, 2) k_eq(const float* __restrict__ eq_b) {
    extern __shared__ float sm[];
    float* At   = sm;            // 2304 : At[d*36 + i]
    float* WK   = sm + 2304;     // 4096 : [d*64+e]  (temp T during prologue)
    float* ROWs = sm + 6400;     // 2048 : [i*64+e]
    float* COLt = sm + 8448;     // 2048 : [e*32+j]
    float* S    = sm + 10496;    // 64
    float* R    = sm + 10560;    // 64
    // total 10624 floats = 42496 B

    int b = blockIdx.x >> 5;
    int k = blockIdx.x & 31;
    int tid = threadIdx.x, warp = tid >> 5, lane = tid & 31;

    const float* W0 = g_wt;
    const float* W1 = g_wt + 1 * 4096;
    const float* W2 = g_wt + 2 * 4096;
    const float* W3 = g_wt + 3 * 4096;
    const float* W4 = g_wt + 4 * 4096;
    const float* W5 = g_wt + 5 * 4096;
    const float* W6 = g_wt + 6 * 4096;
    const float* W7 = g_wt + 7 * 4096;

    for (int idx = tid; idx < 2048; idx += 256) {
        int i = idx >> 6, d = idx & 63;
        At[d * 36 + i] = g_feat[b * 2048 + idx];
    }
    __syncthreads();
    if (tid < 64) {
        float a = 0.f;
#pragma unroll
        for (int i = 0; i < 32; i++) a += At[tid * 36 + i];
        S[tid] = a * (1.f / 32.f);
    }
    __syncthreads();

    float* T = WK;   // reuse as temp
    for (int idx = tid; idx < 4096; idx += 256) {
        int d = idx >> 6;
        float sd = S[d];
        T[idx] = sd * fmaf(At[d * 36 + k], W2[idx], sd * W6[idx]);
    }
    if (tid < 64) {
        float acc = 0.f;
        for (int d = 0; d < 64; d++) {
            float sd = S[d];
            acc += sd * sd * fmaf(At[d * 36 + k], W4[d * 64 + tid], sd * W7[d * 64 + tid]);
        }
        R[tid] = acc + eq_b[tid];
    }
    __syncthreads();

    // ROWs = A @ T_row  (packed over e-pairs)
    for (int idx = tid; idx < 1024; idx += 256) {
        int i = idx >> 5, ep = (idx & 31) * 2;
        ull acc = pk2(0.f, 0.f);
#pragma unroll 8
        for (int d = 0; d < 64; d++) {
            float a = At[d * 36 + i];
            acc = f2fma(pk2(a, a), *(const ull*)(T + d * 64 + ep), acc);
        }
        float2 r = upk2(acc);
        ROWs[i * 64 + ep] = r.x;
        ROWs[i * 64 + ep + 1] = r.y;
    }
    __syncthreads();

    // T = col temp
    for (int idx = tid; idx < 4096; idx += 256) {
        int d = idx >> 6;
        float sd = S[d];
        T[idx] = sd * fmaf(At[d * 36 + k], W1[idx], sd * W5[idx]);
    }
    __syncthreads();

    // COLt[e*32+j]  (packed over e-pairs; j = lane)
    for (int idx = tid; idx < 1024; idx += 256) {
        int ep = (idx >> 5) * 2, j = idx & 31;
        ull acc = pk2(0.f, 0.f);
#pragma unroll 8
        for (int d = 0; d < 64; d++) {
            float a = At[d * 36 + j];
            acc = f2fma(pk2(a, a), *(const ull*)(T + d * 64 + ep), acc);
        }
        float2 r = upk2(acc);
        COLt[ep * 32 + j] = r.x;
        COLt[(ep + 1) * 32 + j] = r.y;
    }
    __syncthreads();

    // final WK[d,e] = a_k[d]*W0 + s[d]*W3
    for (int idx = tid; idx < 4096; idx += 256) {
        int d = idx >> 6;
        WK[idx] = fmaf(At[d * 36 + k], W0[idx], S[d] * W3[idx]);
    }
    __syncthreads();

    int e0 = warp * 8;
    float esum[8] = {0, 0, 0, 0, 0, 0, 0, 0};
    float cbase[8];
#pragma unroll
    for (int t = 0; t < 8; t++) cbase[t] = COLt[(e0 + t) * 32 + lane] + R[e0 + t];

    for (int ig = 0; ig < 4; ig++) {
        int i0 = ig * 8;
        ull acc[8][4];
#pragma unroll
        for (int r = 0; r < 8; r++) {
            const float* rw = ROWs + (i0 + r) * 64 + e0;
#pragma unroll
            for (int p = 0; p < 4; p++)
                acc[r][p] = pk2(cbase[2 * p] + rw[2 * p],
                                cbase[2 * p + 1] + rw[2 * p + 1]);
        }

#pragma unroll 4
        for (int d = 0; d < 64; d++) {
            float aj = At[d * 36 + lane];
            ull aj2 = pk2(aj, aj);
            ull ai01 = *(const ull*)(At + d * 36 + i0);
            ull ai23 = *(const ull*)(At + d * 36 + i0 + 2);
            ull ai45 = *(const ull*)(At + d * 36 + i0 + 4);
            ull ai67 = *(const ull*)(At + d * 36 + i0 + 6);
            ull c01 = f2mul(ai01, aj2);
            ull c23 = f2mul(ai23, aj2);
            ull c45 = f2mul(ai45, aj2);
            ull c67 = f2mul(ai67, aj2);
            float2 cA = upk2(c01), cB = upk2(c23), cC = upk2(c45), cD = upk2(c67);
            ull c0 = pk2(cA.x, cA.x), c1 = pk2(cA.y, cA.y);
            ull c2 = pk2(cB.x, cB.x), c3 = pk2(cB.y, cB.y);
            ull c4 = pk2(cC.x, cC.x), c5 = pk2(cC.y, cC.y);
            ull c6 = pk2(cD.x, cD.x), c7 = pk2(cD.y, cD.y);
            const ull* wp = (const ull*)(WK + d * 64 + e0);
            ull w0 = wp[0], w1 = wp[1], w2 = wp[2], w3 = wp[3];
            acc[0][0] = f2fma(c0, w0, acc[0][0]);
            acc[0][1] = f2fma(c0, w1, acc[0][1]);
            acc[0][2] = f2fma(c0, w2, acc[0][2]);
            acc[0][3] = f2fma(c0, w3, acc[0][3]);
            acc[1][0] = f2fma(c1, w0, acc[1][0]);
            acc[1][1] = f2fma(c1, w1, acc[1][1]);
            acc[1][2] = f2fma(c1, w2, acc[1][2]);
            acc[1][3] = f2fma(c1, w3, acc[1][3]);
            acc[2][0] = f2fma(c2, w0, acc[2][0]);
            acc[2][1] = f2fma(c2, w1, acc[2][1]);
            acc[2][2] = f2fma(c2, w2, acc[2][2]);
            acc[2][3] = f2fma(c2, w3, acc[2][3]);
            acc[3][0] = f2fma(c3, w0, acc[3][0]);
            acc[3][1] = f2fma(c3, w1, acc[3][1]);
            acc[3][2] = f2fma(c3, w2, acc[3][2]);
            acc[3][3] = f2fma(c3, w3, acc[3][3]);
            acc[4][0] = f2fma(c4, w0, acc[4][0]);
            acc[4][1] = f2fma(c4, w1, acc[4][1]);
            acc[4][2] = f2fma(c4, w2, acc[4][2]);
            acc[4][3] = f2fma(c4, w3, acc[4][3]);
            acc[5][0] = f2fma(c5, w0, acc[5][0]);
            acc[5][1] = f2fma(c5, w1, acc[5][1]);
            acc[5][2] = f2fma(c5, w2, acc[5][2]);
            acc[5][3] = f2fma(c5, w3, acc[5][3]);
            acc[6][0] = f2fma(c6, w0, acc[6][0]);
            acc[6][1] = f2fma(c6, w1, acc[6][1]);
            acc[6][2] = f2fma(c6, w2, acc[6][2]);
            acc[6][3] = f2fma(c6, w3, acc[6][3]);
            acc[7][0] = f2fma(c7, w0, acc[7][0]);
            acc[7][1] = f2fma(c7, w1, acc[7][1]);
            acc[7][2] = f2fma(c7, w2, acc[7][2]);
            acc[7][3] = f2fma(c7, w3, acc[7][3]);
        }

#pragma unroll
        for (int r = 0; r < 8; r++)
#pragma unroll
            for (int p = 0; p < 4; p++) {
                float2 v = upk2(acc[r][p]);
                esum[2 * p]     += fmaxf(v.x, 0.f);
                esum[2 * p + 1] += fmaxf(v.y, 0.f);
            }
    }

#pragma unroll
    for (int t = 0; t < 8; t++) {
        float v = esum[t];
#pragma unroll
        for (int off = 16; off; off >>= 1)
            v += __shfl_down_sync(0xffffffffu, v, off);
        if (lane == 0) g_part[blockIdx.x * 64 + e0 + t] = v;
    }
}

// ---------------- kernel 5: reduce over k, relu, final linear -----------------
__global__ void __launch_bounds__(512) k_out(const float* __restrict__ out_w,
                                             const float* __restrict__ out_b,
                                             float* __restrict__ out) {
    int tid = threadIdx.x;
    int bb = tid >> 5;
    int lane = tid & 31;
    float a0 = 0.f, a1 = 0.f;
    for (int k = 0; k < 32; k++) {
        const float* p = g_part + (bb * 32 + k) * 64;
        a0 += p[lane];
        a1 += p[lane + 32];
    }
    float x0 = fmaxf(a0 * (1.f / 32768.f), 0.f);
    float x1 = fmaxf(a1 * (1.f / 32768.f), 0.f);
    float acc = x0 * out_w[lane] + x1 * out_w[lane + 32];
#pragma unroll
    for (int off = 16; off; off >>= 1)
        acc += __shfl_down_sync(0xffffffffu, acc, off);
    if (lane == 0) out[bb] = acc + out_b[0];
}

// ---------------- launch ------------------------------------------------------
extern "C" void kernel_launch(void* const* d_in, const int* in_sizes, int n_in,
                              void* d_out, int out_size) {
    const float* x       = (const float*)d_in[0];
    const float* conv1_w = (const float*)d_in[1];
    const float* conv1_b = (const float*)d_in[2];
    const float* conv2_w = (const float*)d_in[3];
    const float* conv2_b = (const float*)d_in[4];
    const float* fc_w    = (const float*)d_in[5];
    const float* fc_b    = (const float*)d_in[6];
    const float* eq_w    = (const float*)d_in[7];
    const float* eq_b    = (const float*)d_in[8];
    const float* out_w   = (const float*)d_in[9];
    const float* out_b   = (const float*)d_in[10];
    float* out = (float*)d_out;

    cudaFuncSetAttribute(k_conv2, cudaFuncAttributeMaxDynamicSharedMemorySize, 99072);
    cudaFuncSetAttribute(k_eq,    cudaFuncAttributeMaxDynamicSharedMemorySize, 42496);

    k_prep<<<16, 256>>>(eq_w, conv2_w);
    k_conv1<<<NIMG, 224>>>(x, conv1_w, conv1_b);
    k_conv2<<<NIMG, 392, 99072>>>(conv2_b);
    k_fc<<<8 * FC_SPLIT, 256>>>(fc_w);
    k_fcred<<<64, 512>>>(fc_b);
    k_eq<<<NIMG, 256, 42496>>>(eq_b);
    k_out<<<1, 512>>>(out_w, out_b, out);
}